// round 4
// baseline (speedup 1.0000x reference)
#include <cuda_runtime.h>
#include <cstdint>

// ---------------------------------------------------------------------------
// LSTM_41764261986630 : 2-layer LSTM, T=512, B=64, IN=H=512
// Persistent weight-stationary kernel, packed f32x2 FMA edition:
//   128 CTAs x 256 thr; CTA c: layer = c/64, owns 8 hidden units
//   (= 32 ifgo rows, K=1024), weights resident in SMEM, c-state in registers,
//   one grid barrier per wave. k-pairs packed into fma.rn.f32x2.
// ---------------------------------------------------------------------------

#define TSTEPS 512
#define BATCH  64
#define HID    512
#define G4     2048      // 4*H rows of ifgo per layer
#define NCTA   128
#define NTHR   256
#define ROWS   32        // ifgo rows per CTA = 4 gates x 8 hidden
#define HPC    8         // hidden units per CTA
#define WSTR   1028      // padded weight row stride (floats)
#define KC     64        // k-chunk size
#define ASTR   68        // padded activation row stride (floats)
#define BH     (BATCH*HID)   // 32768

// persistent scratch (no cudaMalloc allowed)
__device__ float    g_h0[2][BH];   // double-buffered layer-0 hidden state
__device__ unsigned g_bar;         // monotonic grid-barrier counter (zero-init)

// packed dual-fma: acc.{lo,hi} += a.{lo,hi} * b.{lo,hi}
#define FMA2(acc, a, b) \
    asm("fma.rn.f32x2 %0, %1, %2, %0;" : "+l"(acc) : "l"(a), "l"(b))

__device__ __forceinline__ void cp_async16(float* sdst, const float* gsrc) {
    unsigned sa = (unsigned)__cvta_generic_to_shared(sdst);
    asm volatile("cp.async.cg.shared.global [%0], [%1], 16;\n" :: "r"(sa), "l"(gsrc));
}
__device__ __forceinline__ void cp_commit() { asm volatile("cp.async.commit_group;\n"); }
__device__ __forceinline__ void cp_wait0()  { asm volatile("cp.async.wait_group 0;\n"); }

// Monotonic-counter grid barrier (epoch-relative: safe across graph replays).
__device__ __forceinline__ void grid_sync() {
    __threadfence();
    __syncthreads();
    if (threadIdx.x == 0) {
        unsigned arrive = atomicAdd(&g_bar, 1u);
        unsigned target = (arrive / NCTA + 1u) * NCTA;
        while (*(volatile unsigned*)&g_bar < target) { }
        __threadfence();
    }
    __syncthreads();
}

// Prefetch one 64x64 activation chunk (chunk c: c<8 -> srcA, else srcB)
__device__ __forceinline__ void prefetch_chunk(float* buf, const float* srcA,
                                               const float* srcB, int c, int tid) {
    const float* src = (c < 8) ? srcA : srcB;
    const int kb = (c & 7) * KC;
    #pragma unroll
    for (int it = 0; it < 4; ++it) {
        int flat = it * NTHR + tid;
        int b  = flat >> 4;      // batch row 0..63
        int kq = flat & 15;      // float4 index within chunk
        cp_async16(&buf[b * ASTR + kq * 4], src + b * HID + kb + kq * 4);
    }
    cp_commit();
}

__global__ void __launch_bounds__(NTHR, 1)
lstm_persistent(const float* __restrict__ x, const float* __restrict__ Wx,
                const float* __restrict__ Wh, const float* __restrict__ bh,
                float* __restrict__ out)
{
    extern __shared__ float smem[];
    float* w_s  = smem;                      // [32][1028]
    float* act0 = smem + ROWS * WSTR;        // [64][68]
    float* act1 = act0 + BATCH * ASTR;       // [64][68]

    const int tid   = threadIdx.x;
    const int cta   = blockIdx.x;
    const int layer = cta >> 6;              // 0 or 1
    const int hid0  = (cta & 63) * HPC;      // first hidden unit owned
    const int jj    = tid & 7;               // hidden within CTA (0..7)
    const int gidx  = tid >> 3;              // batch group (0..31); b = gidx + 32*i

    // ---- load this CTA's weight slice into SMEM (stationary for whole run) ----
    // row r = gate*8 + jr  <->  global ifgo row = gate*512 + hid0 + jr
    // k<512: input-path weight; k>=512: recurrent weight Wh
    {
        const float* wx = Wx + (size_t)layer * G4 * HID;
        const float* wh = Wh + (size_t)layer * G4 * HID;
        for (int idx = tid; idx < ROWS * 256; idx += NTHR) {
            int r  = idx >> 8;
            int k  = (idx & 255) * 4;
            int gr = (r >> 3) * HID + hid0 + (r & 7);
            const float* s = (k < HID) ? (wx + (size_t)gr * HID + k)
                                       : (wh + (size_t)gr * HID + (k - HID));
            *(float4*)&w_s[r * WSTR + k] = *(const float4*)s;
        }
    }

    float bias[4];
    #pragma unroll
    for (int g = 0; g < 4; ++g)
        bias[g] = bh[layer * G4 + g * HID + hid0 + jj];

    const float* wrow[4];
    #pragma unroll
    for (int g = 0; g < 4; ++g) wrow[g] = &w_s[(g * 8 + jj) * WSTR];

    float c_st[2] = {0.f, 0.f};
    float h_st[2] = {0.f, 0.f};

    __syncthreads();   // weights ready (per-CTA)

    // ---- wave loop: 513 waves, 1 grid barrier each ----
    for (int w = 0; w <= TSTEPS; ++w) {
        const bool active = (layer == 0) ? (w < TSTEPS) : (w >= 1);
        if (active) {
            const int t = (layer == 0) ? w : (w - 1);
            const float* srcA;
            const float* srcB;
            if (layer == 0) {
                srcA = x + (size_t)t * BH;           // x_t
                srcB = g_h0[(t & 1) ^ 1];            // h0[t-1]
            } else {
                srcA = g_h0[t & 1];                  // h0[t] (written last wave)
                srcB = out + (size_t)(t - 1) * BH;   // h1[t-1] lives in out
            }
            const int nchunk = (t == 0) ? 8 : 16;    // t==0: recurrent half is zero

            // packed accumulators: acc2[gate][i] holds {even-k sum, odd-k sum}
            unsigned long long acc2[4][2];
            #pragma unroll
            for (int g = 0; g < 4; ++g) { acc2[g][0] = 0ull; acc2[g][1] = 0ull; }

            prefetch_chunk(act0, srcA, srcB, 0, tid);

            for (int c = 0; c < nchunk; ++c) {
                cp_wait0();
                __syncthreads();
                if (c + 1 < nchunk)
                    prefetch_chunk((c & 1) ? act0 : act1, srcA, srcB, c + 1, tid);

                const float* ab  = (c & 1) ? act1 : act0;
                const float* ap0 = ab + (gidx     ) * ASTR;
                const float* ap1 = ab + (gidx + 32) * ASTR;
                const int kb = c * KC;

                #pragma unroll
                for (int k4 = 0; k4 < 16; ++k4) {
                    const int ko = k4 * 4;
                    ulonglong2 a0 = *(const ulonglong2*)(ap0 + ko);
                    ulonglong2 a1 = *(const ulonglong2*)(ap1 + ko);
                    #pragma unroll
                    for (int g = 0; g < 4; ++g) {
                        ulonglong2 wv = *(const ulonglong2*)(wrow[g] + kb + ko);
                        FMA2(acc2[g][0], wv.x, a0.x);
                        FMA2(acc2[g][0], wv.y, a0.y);
                        FMA2(acc2[g][1], wv.x, a1.x);
                        FMA2(acc2[g][1], wv.y, a1.y);
                    }
                }
            }

            // ---- horizontal reduce + gates + state update + publish h ----
            const int hh = hid0 + jj;
            float* hdst = (layer == 0) ? g_h0[t & 1] : (out + (size_t)t * BH);
            #pragma unroll
            for (int i = 0; i < 2; ++i) {
                float s[4];
                #pragma unroll
                for (int g = 0; g < 4; ++g) {
                    unsigned long long v = acc2[g][i];
                    float lo = __uint_as_float((unsigned)(v & 0xffffffffull));
                    float hi = __uint_as_float((unsigned)(v >> 32));
                    s[g] = lo + hi + bias[g];
                }
                float ig = 1.f / (1.f + expf(-s[0]));
                float fg = 1.f / (1.f + expf(-s[1]));
                float gt = tanhf(s[2]);
                float og = 1.f / (1.f + expf(-s[3]));
                float cn = fg * c_st[i] + ig * gt;
                c_st[i] = cn;
                float hn = og * tanhf(cn);
                h_st[i] = hn;
                int b = gidx + 32 * i;
                hdst[b * HID + hh] = hn;
            }
        }
        grid_sync();
    }

    // ---- final h, c tails: out layout = [out | h(L,B,H) | c(L,B,H)] ----
    const size_t base = (size_t)TSTEPS * BH;
    const int hh = hid0 + jj;
    #pragma unroll
    for (int i = 0; i < 2; ++i) {
        int b = gidx + 32 * i;
        out[base + (size_t)layer * BH + (size_t)b * HID + hh] = h_st[i];
        out[base + 2 * (size_t)BH + (size_t)layer * BH + (size_t)b * HID + hh] = c_st[i];
    }
}

extern "C" void kernel_launch(void* const* d_in, const int* in_sizes, int n_in,
                              void* d_out, int out_size) {
    (void)in_sizes; (void)n_in; (void)out_size;
    const float* x  = (const float*)d_in[0];
    const float* Wx = (const float*)d_in[1];
    const float* Wh = (const float*)d_in[2];
    const float* bh = (const float*)d_in[3];
    float* out = (float*)d_out;

    const int smem_bytes = (ROWS * WSTR + 2 * BATCH * ASTR) * (int)sizeof(float); // 166400
    cudaFuncSetAttribute(lstm_persistent,
                         cudaFuncAttributeMaxDynamicSharedMemorySize, smem_bytes);
    lstm_persistent<<<NCTA, NTHR, smem_bytes>>>(x, Wx, Wh, bh, out);
}

// round 7
// speedup vs baseline: 3.3433x; 3.3433x over previous
#include <cuda_runtime.h>
#include <cuda_bf16.h>
#include <cstdint>

// ---------------------------------------------------------------------------
// LSTM_41764261986630 : 2-layer LSTM, T=512, B=64, IN=H=512
// mma.sync (HMMA, non-'a' PTX) bf16 3-term split edition.
// 128 persistent CTAs (64/layer), each owns 32 ifgo rows (8 hidden x 4 gates)
// x 64 batch x K=1024.  Weights SMEM-resident (bf16 hi/lo, fragment-ordered),
// acts streamed via 2-stage cp.async in fragment-ordered bf16 hi/lo planes.
// One grid barrier per wave; layer0 does step w, layer1 step w-1.
// R6 fix: prep_x s-decode (e>>10, not e>>9) — x fragment image was scrambled.
// ---------------------------------------------------------------------------

#define TSTEPS 512
#define BATCH  64
#define HID    512
#define BH     (BATCH*HID)
#define NCTA   128
#define NTHR   128

// SMEM byte offsets
#define SO_W    0          // 131072 B : [plane][tile 0..127][256 bf16]
#define SO_A    131072     // 2 stages x (2 planes x 16384 B)
#define SO_BIAS 196608     // 32 floats
#define SMEM_TOTAL 196736

// ---- persistent device scratch (no cudaMalloc allowed) ----
__device__ __align__(16) __nv_bfloat16 g_w[(size_t)NCTA*2*128*256];      // 16MB
__device__ __align__(16) __nv_bfloat16 g_x_hi[(size_t)TSTEPS*32768];     // 32MB
__device__ __align__(16) __nv_bfloat16 g_x_lo[(size_t)TSTEPS*32768];     // 32MB
__device__ __align__(16) __nv_bfloat16 g_h0_hi[2*32768], g_h0_lo[2*32768];
__device__ __align__(16) __nv_bfloat16 g_h1_hi[2*32768], g_h1_lo[2*32768];
__device__ unsigned g_bar;

// ---------------- helpers ----------------
__device__ __forceinline__ void cp_async16(void* sdst, const void* gsrc) {
    unsigned sa;
    asm("{ .reg .u64 t; cvta.to.shared.u64 t, %1; cvt.u32.u64 %0, t; }"
        : "=r"(sa) : "l"(sdst));
    asm volatile("cp.async.cg.shared.global [%0], [%1], 16;\n" :: "r"(sa), "l"(gsrc));
}
#define CP_COMMIT() asm volatile("cp.async.commit_group;\n")
#define CP_WAIT(n)  asm volatile("cp.async.wait_group %0;\n" :: "n"(n))

__device__ __forceinline__ void mma16816(float* d,
        uint32_t a0, uint32_t a1, uint32_t a2, uint32_t a3,
        uint32_t b0, uint32_t b1) {
    asm volatile(
      "mma.sync.aligned.m16n8k16.row.col.f32.bf16.bf16.f32 "
      "{%0,%1,%2,%3}, {%4,%5,%6,%7}, {%8,%9}, {%0,%1,%2,%3};"
      : "+f"(d[0]), "+f"(d[1]), "+f"(d[2]), "+f"(d[3])
      : "r"(a0), "r"(a1), "r"(a2), "r"(a3), "r"(b0), "r"(b1));
}

// fragment-order position of k-local element within a 16-wide act row
__device__ __host__ __forceinline__ int p_of_kl(int kl) {
    return ((kl & 7) >> 1) * 4 + ((kl >> 3) << 1) + (kl & 1);
}

// grid barrier (monotonic counter: safe across graph replays)
__device__ __forceinline__ void grid_sync() {
    __threadfence();
    __syncthreads();
    if (threadIdx.x == 0) {
        unsigned arrive = atomicAdd(&g_bar, 1u);
        unsigned target = (arrive / NCTA + 1u) * NCTA;
        while (*(volatile unsigned*)&g_bar < target) { }
        __threadfence();
    }
    __syncthreads();
}

// ---------------- prep kernels ----------------
// W fragment image per CTA: [plane hi/lo][tile ti = s*2+mb][lane L][8 bf16]
// lane L's 16B = a0..a7 of the m16n8k16 A fragment for rows (mb*16 + m),
// k (s*16 + kl):  m = (L>>2) + (q&1)*8,  kl = (L&3)*2 + (q>>1)*8 + half.
__global__ void prep_w(const float* __restrict__ Wx, const float* __restrict__ Wh) {
    const int blk = blockIdx.x;               // cta*8 + ch
    const int ch = blk & 7, cta = blk >> 3;
    const int layer = cta >> 6, hb = cta & 63;
    const float* wx = Wx + (size_t)layer * 2048 * 512;
    const float* wh = Wh + (size_t)layer * 2048 * 512;
    const size_t base_hi = ((size_t)cta * 2 + 0) * 128 * 256;
    const size_t base_lo = ((size_t)cta * 2 + 1) * 128 * 256;
    for (int e = threadIdx.x; e < 16 * 256; e += blockDim.x) {
        int ti  = ch * 16 + (e >> 8);
        int q16 = e & 255;
        int L = q16 >> 3, eb = q16 & 7;
        int qreg = eb >> 1, half = eb & 1;
        int s = ti >> 1, mb = ti & 1;
        int m  = (L >> 2) + ((qreg & 1) << 3) + (mb << 4);   // row 0..31
        int kl = ((L & 3) << 1) + ((qreg >> 1) << 3) + half;
        int k  = (s << 4) + kl;
        int R  = (m >> 3) * 512 + hb * 8 + (m & 7);
        float v = (k < 512) ? wx[(size_t)R * 512 + k]
                            : wh[(size_t)R * 512 + (k - 512)];
        __nv_bfloat16 hi = __float2bfloat16(v);
        __nv_bfloat16 lo = __float2bfloat16(v - __bfloat162float(hi));
        size_t off = (size_t)ti * 256 + q16;
        g_w[base_hi + off] = hi;
        g_w[base_lo + off] = lo;
    }
}

// x fragment image: [t][s 0..31][n 0..63][16], k-local position p = p_of_kl(kl)
__global__ void prep_x(const float* __restrict__ x) {
    const int t = blockIdx.x;
    const float* src = x + (size_t)t * BH;
    const size_t dst = (size_t)t * 32768;
    for (int e = threadIdx.x; e < 32768; e += blockDim.x) {
        int s = e >> 10, n = (e >> 4) & 63, p = e & 15;   // R6 FIX: s = e>>10
        int q = p >> 2, r = p & 3;
        int kl = (q << 1) + (r & 1) + ((r >> 1) << 3);
        float v = src[n * 512 + ((s << 4) + kl)];
        __nv_bfloat16 hi = __float2bfloat16(v);
        __nv_bfloat16 lo = __float2bfloat16(v - __bfloat162float(hi));
        g_x_hi[dst + e] = hi;
        g_x_lo[dst + e] = lo;
    }
}

// ---------------- main persistent kernel ----------------
__global__ void __launch_bounds__(NTHR, 1)
lstm_mma(const float* __restrict__ bh, float* __restrict__ out)
{
    extern __shared__ __align__(16) char smem[];
    const int tid = threadIdx.x;
    const int L = tid & 31, warp = tid >> 5;
    const int cta = blockIdx.x, layer = cta >> 6, hb = cta & 63;

    // ---- resident weight load (once) ----
    {
        const char* wsrc = (const char*)(g_w + (size_t)cta * 65536);
        for (int i = tid; i < 8192; i += NTHR)
            cp_async16(smem + SO_W + i * 16, wsrc + i * 16);
        CP_COMMIT();
    }
    float* bias_s = (float*)(smem + SO_BIAS);
    if (tid < 32)
        bias_s[tid] = bh[layer * 2048 + (tid >> 3) * 512 + hb * 8 + (tid & 7)];
    CP_WAIT(0);
    __syncthreads();

    // epilogue constants
    const int j  = L >> 2;                 // hidden within CTA (0..7)
    const int hh = hb * 8 + j;             // global hidden index
    const int sH = hh >> 4;
    const int pH = p_of_kl(hh & 15);
    const float bi = bias_s[j],      bf = bias_s[8 + j];
    const float bg = bias_s[16 + j], bo = bias_s[24 + j];

    float c_st[4] = {0.f, 0.f, 0.f, 0.f};
    float h_st[4] = {0.f, 0.f, 0.f, 0.f};

    const int n0 = (warp << 4) + (L >> 2);   // act row for nb=0
    const char* wbase = smem + SO_W;

    for (int w = 0; w <= TSTEPS; ++w) {
        const bool active = (layer == 0) ? (w < TSTEPS) : (w >= 1);
        if (active) {
            const int t = (layer == 0) ? w : (w - 1);
            const int nch = (t == 0) ? 4 : 8;

            const __nv_bfloat16 *Ahi, *Alo, *Bhi, *Blo;
            if (layer == 0) {
                Ahi = g_x_hi + (size_t)t * 32768;  Alo = g_x_lo + (size_t)t * 32768;
                Bhi = g_h0_hi + ((t - 1) & 1) * 32768;
                Blo = g_h0_lo + ((t - 1) & 1) * 32768;
            } else {
                Ahi = g_h0_hi + (t & 1) * 32768;   Alo = g_h0_lo + (t & 1) * 32768;
                Bhi = g_h1_hi + ((t - 1) & 1) * 32768;
                Blo = g_h1_lo + ((t - 1) & 1) * 32768;
            }

            float d[2][2][4];
            #pragma unroll
            for (int mb = 0; mb < 2; ++mb)
                #pragma unroll
                for (int nb = 0; nb < 2; ++nb)
                    #pragma unroll
                    for (int q = 0; q < 4; ++q) d[mb][nb][q] = 0.f;

            // prefetch helper (chunk c -> stage c&1, both planes 16KB each)
            auto prefetch = [&](int c) {
                const int st = c & 1;
                const __nv_bfloat16* shi = (c < 4) ? Ahi + c * 8192 : Bhi + (c - 4) * 8192;
                const __nv_bfloat16* slo = (c < 4) ? Alo + c * 8192 : Blo + (c - 4) * 8192;
                char* dhi = smem + SO_A + st * 32768;
                char* dlo = dhi + 16384;
                #pragma unroll
                for (int i = 0; i < 8; ++i) {
                    int e = i * NTHR + tid;
                    cp_async16(dhi + e * 16, (const char*)shi + e * 16);
                    cp_async16(dlo + e * 16, (const char*)slo + e * 16);
                }
                CP_COMMIT();
            };

            prefetch(0);
            for (int c = 0; c < nch; ++c) {
                if (c + 1 < nch) { prefetch(c + 1); CP_WAIT(1); }
                else             { CP_WAIT(0); }
                __syncthreads();

                const char* ahi = smem + SO_A + (c & 1) * 32768;
                const char* alo = ahi + 16384;
                #pragma unroll
                for (int sl = 0; sl < 8; ++sl) {
                    const int s2 = ((c << 3) + sl) << 1;   // tile = s*2 (+mb)
                    // W fragments (lane-linear LDS.128)
                    uint4 wh0 = *(const uint4*)(wbase + (size_t)(      s2    ) * 512 + L * 16);
                    uint4 wh1 = *(const uint4*)(wbase + (size_t)(      s2 + 1) * 512 + L * 16);
                    uint4 wl0 = *(const uint4*)(wbase + (size_t)(128 + s2    ) * 512 + L * 16);
                    uint4 wl1 = *(const uint4*)(wbase + (size_t)(128 + s2 + 1) * 512 + L * 16);
                    // act fragments (lane-linear LDS.64)
                    const int ro0 = ((sl << 6) + n0) * 32 + (L & 3) * 8;
                    const int ro1 = ro0 + 8 * 32;
                    uint2 ah0 = *(const uint2*)(ahi + ro0);
                    uint2 ah1 = *(const uint2*)(ahi + ro1);
                    uint2 al0 = *(const uint2*)(alo + ro0);
                    uint2 al1 = *(const uint2*)(alo + ro1);

                    mma16816(d[0][0], wh0.x, wh0.y, wh0.z, wh0.w, ah0.x, ah0.y);
                    mma16816(d[0][0], wh0.x, wh0.y, wh0.z, wh0.w, al0.x, al0.y);
                    mma16816(d[0][0], wl0.x, wl0.y, wl0.z, wl0.w, ah0.x, ah0.y);

                    mma16816(d[0][1], wh0.x, wh0.y, wh0.z, wh0.w, ah1.x, ah1.y);
                    mma16816(d[0][1], wh0.x, wh0.y, wh0.z, wh0.w, al1.x, al1.y);
                    mma16816(d[0][1], wl0.x, wl0.y, wl0.z, wl0.w, ah1.x, ah1.y);

                    mma16816(d[1][0], wh1.x, wh1.y, wh1.z, wh1.w, ah0.x, ah0.y);
                    mma16816(d[1][0], wh1.x, wh1.y, wh1.z, wh1.w, al0.x, al0.y);
                    mma16816(d[1][0], wl1.x, wl1.y, wl1.z, wl1.w, ah0.x, ah0.y);

                    mma16816(d[1][1], wh1.x, wh1.y, wh1.z, wh1.w, ah1.x, ah1.y);
                    mma16816(d[1][1], wh1.x, wh1.y, wh1.z, wh1.w, al1.x, al1.y);
                    mma16816(d[1][1], wl1.x, wl1.y, wl1.z, wl1.w, ah1.x, ah1.y);
                }
                __syncthreads();
            }

            // ---- epilogue: pure-register gates; republish h (frag order) ----
            __nv_bfloat16* dh_hi = (layer ? g_h1_hi : g_h0_hi) + (t & 1) * 32768;
            __nv_bfloat16* dh_lo = (layer ? g_h1_lo : g_h0_lo) + (t & 1) * 32768;
            float* orow = out + (size_t)t * BH;
            #pragma unroll
            for (int nb = 0; nb < 2; ++nb) {
                #pragma unroll
                for (int cc = 0; cc < 2; ++cc) {
                    const int si = nb * 2 + cc;
                    const int b  = (warp << 4) + (nb << 3) + ((L & 3) << 1) + cc;
                    float pi = d[0][nb][cc]     + bi;
                    float pf = d[0][nb][2 + cc] + bf;
                    float pg = d[1][nb][cc]     + bg;
                    float po = d[1][nb][2 + cc] + bo;
                    float ig = __fdividef(1.f, 1.f + __expf(-pi));
                    float fg = __fdividef(1.f, 1.f + __expf(-pf));
                    float gt = 2.f * __fdividef(1.f, 1.f + __expf(-2.f * pg)) - 1.f;
                    float og = __fdividef(1.f, 1.f + __expf(-po));
                    float cn = fg * c_st[si] + ig * gt;
                    c_st[si] = cn;
                    float th = 2.f * __fdividef(1.f, 1.f + __expf(-2.f * cn)) - 1.f;
                    float hn = og * th;
                    h_st[si] = hn;
                    __nv_bfloat16 hhi = __float2bfloat16(hn);
                    __nv_bfloat16 hlo = __float2bfloat16(hn - __bfloat162float(hhi));
                    const int idx = sH * 1024 + b * 16 + pH;
                    dh_hi[idx] = hhi;
                    dh_lo[idx] = hlo;
                    if (layer == 1) orow[b * 512 + hh] = hn;
                }
            }
        }
        grid_sync();
    }

    // ---- final h, c tails: out layout = [out | h(L,B,H) | c(L,B,H)] ----
    const size_t base = (size_t)TSTEPS * BH;
    #pragma unroll
    for (int nb = 0; nb < 2; ++nb)
        #pragma unroll
        for (int cc = 0; cc < 2; ++cc) {
            const int si = nb * 2 + cc;
            const int b  = (warp << 4) + (nb << 3) + ((L & 3) << 1) + cc;
            out[base + (size_t)layer * BH + (size_t)b * 512 + hh] = h_st[si];
            out[base + 2 * (size_t)BH + (size_t)layer * BH + (size_t)b * 512 + hh] = c_st[si];
        }
}

extern "C" void kernel_launch(void* const* d_in, const int* in_sizes, int n_in,
                              void* d_out, int out_size) {
    (void)in_sizes; (void)n_in; (void)out_size;
    const float* x  = (const float*)d_in[0];
    const float* Wx = (const float*)d_in[1];
    const float* Wh = (const float*)d_in[2];
    const float* bh = (const float*)d_in[3];
    float* out = (float*)d_out;

    prep_w<<<NCTA * 8, 128>>>(Wx, Wh);
    prep_x<<<TSTEPS, 256>>>(x);

    cudaFuncSetAttribute(lstm_mma, cudaFuncAttributeMaxDynamicSharedMemorySize,
                         SMEM_TOTAL);
    lstm_mma<<<NCTA, NTHR, SMEM_TOTAL>>>(bh, out);
}